// round 15
// baseline (speedup 1.0000x reference)
#include <cuda_runtime.h>
#include <cuda_bf16.h>
#include <cstdint>

#define NN 100000
#define NE 800000
#define H  64
#define NT 256
#define NBLK 391
#define PPIT 144   // proj smem row pitch bytes (72 bf16)
#define UPIT 272   // upd smem row pitch bytes (136 bf16)

#define SMEM_PROJT (4 * 128 * PPIT)                          // AH AL BH BL
#define SMEM_UPDT  (2 * 128 * UPIT + 2 * 64 * UPIT + 1280)   // AH AL BH BL + params + final acc

// Scratch (device globals: allocation-free rule)
__device__ __align__(16) float g_p1[(size_t)NN * H];
__device__ __align__(16) float g_p2[(size_t)NN * H];
__device__ __align__(16) __nv_bfloat162 g_xh[(size_t)NN * 32];
__device__ __align__(16) __nv_bfloat162 g_xl[(size_t)NN * 32];
__device__ __align__(16) __nv_bfloat162 g_ah[(size_t)NN * 32];
__device__ __align__(16) __nv_bfloat162 g_al[(size_t)NN * 32];
__device__ __align__(16) __nv_bfloat16 g_bh[3 * 128 * 72];   // proj W hi [C][k] pitch 72
__device__ __align__(16) __nv_bfloat16 g_bl[3 * 128 * 72];
__device__ __align__(16) __nv_bfloat16 g_uh[3 * 64 * 136];   // upd W hi [C][k] pitch 136
__device__ __align__(16) __nv_bfloat16 g_ul[3 * 64 * 136];
__device__ int g_deg[NN];
__device__ int g_off[NN + 1];
__device__ int g_cur[NN];
__device__ int g_csr[NE];
__device__ int g_bsum[NBLK];
__device__ int g_boff[NBLK];
__device__ float g_sum[H];
__device__ unsigned g_maxb[H];

// ---------- helpers ----------
__device__ __forceinline__ unsigned encf(float f) {
    unsigned u = __float_as_uint(f);
    return (u & 0x80000000u) ? ~u : (u | 0x80000000u);
}
__device__ __forceinline__ float decf(unsigned u) {
    return (u & 0x80000000u) ? __uint_as_float(u & 0x7FFFFFFFu) : __uint_as_float(~u);
}
__device__ __forceinline__ void split2(float a, float b, __nv_bfloat162& h, __nv_bfloat162& lo) {
    __nv_bfloat16 ha = __float2bfloat16(a), hb = __float2bfloat16(b);
    h = __halves2bfloat162(ha, hb);
    lo = __halves2bfloat162(__float2bfloat16(a - __bfloat162float(ha)),
                            __float2bfloat16(b - __bfloat162float(hb)));
}
__device__ __forceinline__ void ldsm4(unsigned* r, uint32_t addr) {
    asm volatile("ldmatrix.sync.aligned.m8n8.x4.shared.b16 {%0,%1,%2,%3}, [%4];"
                 : "=r"(r[0]), "=r"(r[1]), "=r"(r[2]), "=r"(r[3]) : "r"(addr));
}
__device__ __forceinline__ void mma16816(float* c, const unsigned* a, const unsigned* b) {
    asm volatile("mma.sync.aligned.m16n8k16.row.col.f32.bf16.bf16.f32 "
                 "{%0,%1,%2,%3}, {%4,%5,%6,%7}, {%8,%9}, {%0,%1,%2,%3};"
                 : "+f"(c[0]), "+f"(c[1]), "+f"(c[2]), "+f"(c[3])
                 : "r"(a[0]), "r"(a[1]), "r"(a[2]), "r"(a[3]), "r"(b[0]), "r"(b[1]));
}
__device__ __forceinline__ void cpa16(void* dst, const void* src) {
    unsigned d = (unsigned)__cvta_generic_to_shared(dst);
    asm volatile("cp.async.ca.shared.global [%0], [%1], 16;" :: "r"(d), "l"(src));
}
#define CPA_COMMIT() asm volatile("cp.async.commit_group;")
#define CPA_WAIT0()  asm volatile("cp.async.wait_group 0;")

// ---------- merged setup: embed + weight prepack ----------
__global__ void k_setup(const int* __restrict__ ti, const float* __restrict__ et,
                        const float* __restrict__ msg_w, const float* __restrict__ upd_w) {
    int i = blockIdx.x * blockDim.x + threadIdx.x;
    int stride = gridDim.x * blockDim.x;
    for (int n = i; n < NN; n += stride) g_deg[n] = 0;
    if (i < H) { g_sum[i] = 0.f; g_maxb[i] = 0u; }
    for (int lin = i; lin < NN * 16; lin += stride) {
        int n = lin >> 4, q = lin & 15;
        float4 v = ((const float4*)et)[ti[n] * 16 + q];
        __nv_bfloat162 h0, l0, h1, l1;
        split2(v.x, v.y, h0, l0);
        split2(v.z, v.w, h1, l1);
        g_xh[lin * 2] = h0; g_xh[lin * 2 + 1] = h1;
        g_xl[lin * 2] = l0; g_xl[lin * 2 + 1] = l1;
    }
    for (int idx = i; idx < 3 * 128 * 72; idx += stride) {
        int l = idx / (128 * 72), r = idx % (128 * 72);
        int C = r / 72, k = r % 72;
        __nv_bfloat16 h = __float2bfloat16(0.f), lo = h;
        if (k < 64) {
            float v = msg_w[l * 8192 + (k + (C & 64)) * 64 + (C & 63)];
            h = __float2bfloat16(v);
            lo = __float2bfloat16(v - __bfloat162float(h));
        }
        g_bh[idx] = h; g_bl[idx] = lo;
    }
    for (int idx = i; idx < 3 * 64 * 136; idx += stride) {
        int l = idx / (64 * 136), r = idx % (64 * 136);
        int C = r / 136, k = r % 136;
        __nv_bfloat16 h = __float2bfloat16(0.f), lo = h;
        if (k < 128) {
            float v = upd_w[l * 8192 + k * 64 + C];
            h = __float2bfloat16(v);
            lo = __float2bfloat16(v - __bfloat162float(h));
        }
        g_uh[idx] = h; g_ul[idx] = lo;
    }
}

__global__ void k_hist(const int* __restrict__ edges) {
    int i = blockIdx.x * blockDim.x + threadIdx.x;
    int stride = gridDim.x * blockDim.x;
    for (int e = i; e < NE; e += stride)
        atomicAdd(&g_deg[((const int2*)edges)[e].y], 1);
}

// ---------- exclusive scan ----------
__global__ void k_scan1() {
    __shared__ int s[256];
    int t = threadIdx.x;
    int i = blockIdx.x * 256 + t;
    int v = (i < NN) ? g_deg[i] : 0;
    s[t] = v;
    __syncthreads();
    #pragma unroll
    for (int d = 1; d < 256; d <<= 1) {
        int tv = (t >= d) ? s[t - d] : 0;
        __syncthreads();
        s[t] += tv;
        __syncthreads();
    }
    if (i < NN) g_off[i] = s[t] - v;
    if (t == 255) g_bsum[blockIdx.x] = s[255];
}

__global__ void k_scan2() {
    __shared__ int s[512];
    int t = threadIdx.x;
    int v = (t < NBLK) ? g_bsum[t] : 0;
    s[t] = v;
    __syncthreads();
    #pragma unroll
    for (int d = 1; d < 512; d <<= 1) {
        int tv = (t >= d) ? s[t - d] : 0;
        __syncthreads();
        s[t] += tv;
        __syncthreads();
    }
    if (t < NBLK) g_boff[t] = s[t] - v;
}

__global__ void k_scan3() {
    int i = blockIdx.x * blockDim.x + threadIdx.x;
    if (i < NN) {
        int val = g_off[i] + g_boff[i >> 8];
        g_off[i] = val;
        g_cur[i] = val;
    }
    if (i == 0) g_off[NN] = NE;
}

__global__ void k_scatter(const int* __restrict__ edges) {
    int e = blockIdx.x * blockDim.x + threadIdx.x;
    if (e < NE) {
        int2 ed = ((const int2*)edges)[e];
        int pos = atomicAdd(&g_cur[ed.y], 1);
        g_csr[pos] = ed.x;
    }
}

// ---------- tensor-core projection (4M x 2N warp tiling) ----------
// warp w: rows (w&3)*32 .. +32, cols (w>>2)*64 .. +64
__global__ __launch_bounds__(256, 2) void k_proj_t(int layer, const float* __restrict__ msg_b) {
    extern __shared__ char smc[];
    char* AH = smc;
    char* AL = AH + 128 * PPIT;
    char* BH = AL + 128 * PPIT;
    char* BL = BH + 128 * PPIT;

    const int tid = threadIdx.x;
    const int w = tid >> 5, l = tid & 31;
    const int mrow = (w & 3) * 32;      // warp row base
    const int c64 = (w >> 2) * 64;      // warp col base (0 -> P1, 64 -> P2)

    {
        const uint4* sh = (const uint4*)(g_bh + layer * 128 * 72);
        const uint4* sl = (const uint4*)(g_bl + layer * 128 * 72);
        for (int i = tid; i < 1152; i += 256) {
            ((uint4*)BH)[i] = sh[i];
            ((uint4*)BL)[i] = sl[i];
        }
    }
    // bias pairs for P2 warps (col within 64-group = i*8 + cc)
    float2 bias2[8];
    #pragma unroll
    for (int i = 0; i < 8; i++) bias2[i] = *(const float2*)(msg_b + i * 8 + (l & 3) * 2);

    const uint32_t a_loff = (uint32_t)((mrow + (l & 15)) * PPIT) + ((l >> 4) ? 16u : 0u);
    const uint32_t b_loff = (uint32_t)((l & 7) * PPIT) + (((l >> 3) & 1) ? 16u : 0u)
                          + (((l >> 4) & 1) ? 8u * PPIT : 0u)
                          + (uint32_t)(c64 * PPIT);
    const uint32_t aH = (uint32_t)__cvta_generic_to_shared(AH) + a_loff;
    const uint32_t aL = (uint32_t)__cvta_generic_to_shared(AL) + a_loff;
    const uint32_t bH = (uint32_t)__cvta_generic_to_shared(BH) + b_loff;
    const uint32_t bL = (uint32_t)__cvta_generic_to_shared(BL) + b_loff;

    const uint4* xh4 = (const uint4*)g_xh;
    const uint4* xl4 = (const uint4*)g_xl;

    const int ntiles = (NN + 127) / 128;

    auto stageA = [&](int base) {
        #pragma unroll
        for (int s = 0; s < 4; s++) {
            int i = s * 256 + tid;
            int r = i >> 3, q = i & 7;
            int gn = base + r; if (gn >= NN) gn = NN - 1;
            cpa16(AH + r * PPIT + q * 16, &xh4[gn * 8 + q]);
            cpa16(AL + r * PPIT + q * 16, &xl4[gn * 8 + q]);
        }
    };

    if (blockIdx.x < ntiles) stageA(blockIdx.x * 128);
    CPA_COMMIT();

    for (int tile = blockIdx.x; tile < ntiles; tile += gridDim.x) {
        const int base = tile * 128;
        CPA_WAIT0();
        __syncthreads();

        // C frag index: rb*8 + ntp*2 + p (rb: rowblock 0/1, ntp: 16-col group, p: 8-col half)
        float C[16][4];
        #pragma unroll
        for (int nt = 0; nt < 16; nt++) {
            C[nt][0] = 0.f; C[nt][1] = 0.f; C[nt][2] = 0.f; C[nt][3] = 0.f;
        }

        #pragma unroll
        for (int ks = 0; ks < 4; ks++) {
            unsigned Ah0[4], Al0[4], Ah1[4], Al1[4];
            ldsm4(Ah0, aH + ks * 32);
            ldsm4(Al0, aL + ks * 32);
            ldsm4(Ah1, aH + 16 * PPIT + ks * 32);
            ldsm4(Al1, aL + 16 * PPIT + ks * 32);
            #pragma unroll
            for (int ntp = 0; ntp < 4; ntp++) {
                unsigned Bh[4], Bl[4];
                ldsm4(Bh, bH + ntp * 16 * PPIT + ks * 32);
                ldsm4(Bl, bL + ntp * 16 * PPIT + ks * 32);
                float* c00 = C[ntp * 2];
                float* c01 = C[ntp * 2 + 1];
                float* c10 = C[8 + ntp * 2];
                float* c11 = C[8 + ntp * 2 + 1];
                mma16816(c00, Ah0, Bh); mma16816(c00, Ah0, Bl); mma16816(c00, Al0, Bh);
                mma16816(c01, Ah0, Bh + 2); mma16816(c01, Ah0, Bl + 2); mma16816(c01, Al0, Bh + 2);
                mma16816(c10, Ah1, Bh); mma16816(c10, Ah1, Bl); mma16816(c10, Al1, Bh);
                mma16816(c11, Ah1, Bh + 2); mma16816(c11, Ah1, Bl + 2); mma16816(c11, Al1, Bh + 2);
            }
        }
        __syncthreads();

        int nxt = tile + gridDim.x;
        if (nxt < ntiles) stageA(nxt * 128);
        CPA_COMMIT();

        const int cc = (l & 3) * 2;
        const int rb0 = base + mrow + (l >> 2);
        #pragma unroll
        for (int rb = 0; rb < 2; rb++) {
            int r0 = rb0 + rb * 16;
            int r1 = r0 + 8;
            #pragma unroll
            for (int i = 0; i < 8; i++) {   // i = ntp*2 + p
                const float* cf = C[rb * 8 + i];
                int col = i * 8 + cc;       // col within this warp's 64-group
                if (c64 == 0) {
                    if (r0 < NN) *(float2*)(g_p1 + (size_t)r0 * H + col) = make_float2(cf[0], cf[1]);
                    if (r1 < NN) *(float2*)(g_p1 + (size_t)r1 * H + col) = make_float2(cf[2], cf[3]);
                } else {
                    float2 bb = bias2[i];
                    if (r0 < NN) *(float2*)(g_p2 + (size_t)r0 * H + col) =
                        make_float2(cf[0] + bb.x, cf[1] + bb.y);
                    if (r1 < NN) *(float2*)(g_p2 + (size_t)r1 * H + col) =
                        make_float2(cf[2] + bb.x, cf[3] + bb.y);
                }
            }
        }
    }
}

// ---------- CSR edge pass (4-way unrolled): agg[n] -> bf16 hi/lo ----------
__global__ __launch_bounds__(NT) void k_edge() {
    int idx = blockIdx.x * NT + threadIdx.x;
    int n = idx >> 3, q = idx & 7;
    int s0 = g_off[n], s1 = g_off[n + 1];
    const float4* p2 = (const float4*)(g_p2 + (size_t)n * H) + q * 2;
    float4 b0 = p2[0], b1 = p2[1];
    float a[8] = {0.f, 0.f, 0.f, 0.f, 0.f, 0.f, 0.f, 0.f};
    int i = s0;
    for (; i + 4 <= s1; i += 4) {
        int sA = g_csr[i], sB = g_csr[i + 1], sC = g_csr[i + 2], sD = g_csr[i + 3];
        const float4* pA = (const float4*)(g_p1 + (size_t)sA * H) + q * 2;
        const float4* pB = (const float4*)(g_p1 + (size_t)sB * H) + q * 2;
        const float4* pC = (const float4*)(g_p1 + (size_t)sC * H) + q * 2;
        const float4* pD = (const float4*)(g_p1 + (size_t)sD * H) + q * 2;
        float4 cA0 = pA[0], cA1 = pA[1];
        float4 cB0 = pB[0], cB1 = pB[1];
        float4 cC0 = pC[0], cC1 = pC[1];
        float4 cD0 = pD[0], cD1 = pD[1];
        a[0] += fmaxf(cA0.x + b0.x, 0.f) + fmaxf(cB0.x + b0.x, 0.f)
              + fmaxf(cC0.x + b0.x, 0.f) + fmaxf(cD0.x + b0.x, 0.f);
        a[1] += fmaxf(cA0.y + b0.y, 0.f) + fmaxf(cB0.y + b0.y, 0.f)
              + fmaxf(cC0.y + b0.y, 0.f) + fmaxf(cD0.y + b0.y, 0.f);
        a[2] += fmaxf(cA0.z + b0.z, 0.f) + fmaxf(cB0.z + b0.z, 0.f)
              + fmaxf(cC0.z + b0.z, 0.f) + fmaxf(cD0.z + b0.z, 0.f);
        a[3] += fmaxf(cA0.w + b0.w, 0.f) + fmaxf(cB0.w + b0.w, 0.f)
              + fmaxf(cC0.w + b0.w, 0.f) + fmaxf(cD0.w + b0.w, 0.f);
        a[4] += fmaxf(cA1.x + b1.x, 0.f) + fmaxf(cB1.x + b1.x, 0.f)
              + fmaxf(cC1.x + b1.x, 0.f) + fmaxf(cD1.x + b1.x, 0.f);
        a[5] += fmaxf(cA1.y + b1.y, 0.f) + fmaxf(cB1.y + b1.y, 0.f)
              + fmaxf(cC1.y + b1.y, 0.f) + fmaxf(cD1.y + b1.y, 0.f);
        a[6] += fmaxf(cA1.z + b1.z, 0.f) + fmaxf(cB1.z + b1.z, 0.f)
              + fmaxf(cC1.z + b1.z, 0.f) + fmaxf(cD1.z + b1.z, 0.f);
        a[7] += fmaxf(cA1.w + b1.w, 0.f) + fmaxf(cB1.w + b1.w, 0.f)
              + fmaxf(cC1.w + b1.w, 0.f) + fmaxf(cD1.w + b1.w, 0.f);
    }
    for (; i < s1; i++) {
        int src = g_csr[i];
        const float4* p1 = (const float4*)(g_p1 + (size_t)src * H) + q * 2;
        float4 c0 = p1[0], c1 = p1[1];
        a[0] += fmaxf(c0.x + b0.x, 0.f); a[1] += fmaxf(c0.y + b0.y, 0.f);
        a[2] += fmaxf(c0.z + b0.z, 0.f); a[3] += fmaxf(c0.w + b0.w, 0.f);
        a[4] += fmaxf(c1.x + b1.x, 0.f); a[5] += fmaxf(c1.y + b1.y, 0.f);
        a[6] += fmaxf(c1.z + b1.z, 0.f); a[7] += fmaxf(c1.w + b1.w, 0.f);
    }
    float ic = 1.0f / fmaxf((float)(s1 - s0), 1.0f);
    __nv_bfloat162 h[4], lo[4];
    #pragma unroll
    for (int j = 0; j < 4; j++) split2(a[2 * j] * ic, a[2 * j + 1] * ic, h[j], lo[j]);
    *(uint4*)(g_ah + (size_t)n * 32 + q * 4) = *(uint4*)h;
    *(uint4*)(g_al + (size_t)n * 32 + q * 4) = *(uint4*)lo;
}

// ---------- tensor-core update + residual (from smem) + LayerNorm (+final reduce) ----------
template <bool FINAL>
__global__ __launch_bounds__(256, 2) void k_upd_t(int layer, const float* __restrict__ B,
                                                  const float* __restrict__ lng,
                                                  const float* __restrict__ lnb) {
    extern __shared__ char smc[];
    char* AH = smc;
    char* AL = AH + 128 * UPIT;
    char* BH = AL + 128 * UPIT;
    char* BL = BH + 64 * UPIT;
    float* prm = (float*)(BL + 64 * UPIT);           // bias[64], g[64], b2[64]
    float* fsum = prm + 192;
    unsigned* fmax = (unsigned*)(fsum + 64);

    const int tid = threadIdx.x;
    const int w = tid >> 5, l = tid & 31;

    {
        const uint4* sh = (const uint4*)(g_uh + layer * 64 * 136);
        const uint4* sl = (const uint4*)(g_ul + layer * 64 * 136);
        for (int i = tid; i < 1088; i += 256) {
            ((uint4*)BH)[i] = sh[i];
            ((uint4*)BL)[i] = sl[i];
        }
        if (tid < 64) {
            prm[tid] = B[tid];
            prm[64 + tid] = lng[tid];
            prm[128 + tid] = lnb[tid];
            if (FINAL) { fsum[tid] = 0.f; fmax[tid] = 0u; }
        }
    }

    const uint32_t a_loff = (uint32_t)(((w << 4) + (l & 15)) * UPIT) + ((l >> 4) ? 16u : 0u);
    const uint32_t b_loff = (uint32_t)((l & 7) * UPIT) + (((l >> 3) & 1) ? 16u : 0u)
                          + (((l >> 4) & 1) ? 8u * UPIT : 0u);
    const uint32_t aH = (uint32_t)__cvta_generic_to_shared(AH) + a_loff;
    const uint32_t aL = (uint32_t)__cvta_generic_to_shared(AL) + a_loff;
    const uint32_t bH = (uint32_t)__cvta_generic_to_shared(BH) + b_loff;
    const uint32_t bL = (uint32_t)__cvta_generic_to_shared(BL) + b_loff;

    const uint4* xh4 = (const uint4*)g_xh;
    const uint4* xl4 = (const uint4*)g_xl;
    const uint4* ah4 = (const uint4*)g_ah;
    const uint4* al4 = (const uint4*)g_al;

    const int ntiles = (NN + 127) / 128;

    auto stageA = [&](int base) {
        #pragma unroll
        for (int s = 0; s < 8; s++) {
            int i = s * 256 + tid;
            int r = i >> 4, q = i & 15;
            int gn = base + r; if (gn >= NN) gn = NN - 1;
            const uint4* srch = (q < 8) ? &xh4[gn * 8 + q] : &ah4[gn * 8 + (q - 8)];
            const uint4* srcl = (q < 8) ? &xl4[gn * 8 + q] : &al4[gn * 8 + (q - 8)];
            cpa16(AH + r * UPIT + q * 16, srch);
            cpa16(AL + r * UPIT + q * 16, srcl);
        }
    };

    float ls[16], lm[16];
    if (FINAL) {
        #pragma unroll
        for (int i = 0; i < 16; i++) { ls[i] = 0.f; lm[i] = -3.402823466e38f; }
    }

    if (blockIdx.x < ntiles) stageA(blockIdx.x * 128);
    CPA_COMMIT();

    const int lr0 = (w << 4) + (l >> 2);
    const int lr1 = lr0 + 8;
    const int cc = (l & 3) * 2;

    for (int tile = blockIdx.x; tile < ntiles; tile += gridDim.x) {
        const int base = tile * 128;
        CPA_WAIT0();
        __syncthreads();

        float C[8][4];
        #pragma unroll
        for (int nt = 0; nt < 8; nt++) {
            C[nt][0] = 0.f; C[nt][1] = 0.f; C[nt][2] = 0.f; C[nt][3] = 0.f;
        }

        #pragma unroll
        for (int ks = 0; ks < 8; ks++) {
            unsigned Ah[4], Al4r[4];
            ldsm4(Ah, aH + ks * 32);
            ldsm4(Al4r, aL + ks * 32);
            #pragma unroll
            for (int ntp = 0; ntp < 4; ntp++) {
                unsigned Bh[4], Bl[4];
                ldsm4(Bh, bH + ntp * 16 * UPIT + ks * 32);
                ldsm4(Bl, bL + ntp * 16 * UPIT + ks * 32);
                mma16816(C[2 * ntp],     Ah,   Bh);
                mma16816(C[2 * ntp],     Ah,   Bl);
                mma16816(C[2 * ntp],     Al4r, Bh);
                mma16816(C[2 * ntp + 1], Ah,   Bh + 2);
                mma16816(C[2 * ntp + 1], Ah,   Bl + 2);
                mma16816(C[2 * ntp + 1], Al4r, Bh + 2);
            }
        }
        __syncthreads();

        // residual x = xh + xl from smem (this tile's A, x-half = first 128 bf16 cols)
        float rx0[16], rx1[16];
        #pragma unroll
        for (int nt = 0; nt < 8; nt++) {
            int boff = (nt * 8 + cc) * 2;
            __nv_bfloat162 h0 = *(__nv_bfloat162*)(AH + lr0 * UPIT + boff);
            __nv_bfloat162 l0 = *(__nv_bfloat162*)(AL + lr0 * UPIT + boff);
            __nv_bfloat162 h1 = *(__nv_bfloat162*)(AH + lr1 * UPIT + boff);
            __nv_bfloat162 l1 = *(__nv_bfloat162*)(AL + lr1 * UPIT + boff);
            rx0[2 * nt]     = __bfloat162float(h0.x) + __bfloat162float(l0.x);
            rx0[2 * nt + 1] = __bfloat162float(h0.y) + __bfloat162float(l0.y);
            rx1[2 * nt]     = __bfloat162float(h1.x) + __bfloat162float(l1.x);
            rx1[2 * nt + 1] = __bfloat162float(h1.y) + __bfloat162float(l1.y);
        }
        __syncthreads();

        int nxt = tile + gridDim.x;
        if (nxt < ntiles) stageA(nxt * 128);
        CPA_COMMIT();

        int rr0 = base + lr0;
        int rr1 = base + lr1;
        float h0[8], h1[8];
        float s1a = 0.f, s2a = 0.f, s1b = 0.f, s2b = 0.f;
        #pragma unroll
        for (int nt = 0; nt < 8; nt++) {
            int col = nt * 8 + cc;
            float bx = prm[col], by = prm[col + 1];
            float v0 = fmaxf(C[nt][0] + bx, 0.f) + rx0[2 * nt];
            float v1 = fmaxf(C[nt][1] + by, 0.f) + rx0[2 * nt + 1];
            float v2 = fmaxf(C[nt][2] + bx, 0.f) + rx1[2 * nt];
            float v3 = fmaxf(C[nt][3] + by, 0.f) + rx1[2 * nt + 1];
            h0[nt] = v0; h1[nt] = v2;
            s1a += v0 + v1; s2a += v0 * v0 + v1 * v1;
            s1b += v2 + v3; s2b += v2 * v2 + v3 * v3;
            C[nt][1] = v1; C[nt][3] = v3;
        }
        #pragma unroll
        for (int d = 1; d < 4; d <<= 1) {
            s1a += __shfl_xor_sync(0xFFFFFFFFu, s1a, d);
            s2a += __shfl_xor_sync(0xFFFFFFFFu, s2a, d);
            s1b += __shfl_xor_sync(0xFFFFFFFFu, s1b, d);
            s2b += __shfl_xor_sync(0xFFFFFFFFu, s2b, d);
        }
        float mua = s1a * 0.015625f, mub = s1b * 0.015625f;
        float sca = rsqrtf(fmaxf(s2a * 0.015625f - mua * mua, 0.f) + 1e-5f);
        float scb = rsqrtf(fmaxf(s2b * 0.015625f - mub * mub, 0.f) + 1e-5f);
        #pragma unroll
        for (int nt = 0; nt < 8; nt++) {
            int col = nt * 8 + cc;
            float gx = prm[64 + col], gy = prm[65 + col];
            float bx = prm[128 + col], by = prm[129 + col];
            if (rr0 < NN) {
                float o0 = (h0[nt] - mua) * sca * gx + bx;
                float o1 = (C[nt][1] - mua) * sca * gy + by;
                if (FINAL) {
                    ls[2 * nt] += o0; ls[2 * nt + 1] += o1;
                    lm[2 * nt] = fmaxf(lm[2 * nt], o0);
                    lm[2 * nt + 1] = fmaxf(lm[2 * nt + 1], o1);
                } else {
                    __nv_bfloat162 hh, ll;
                    split2(o0, o1, hh, ll);
                    g_xh[(size_t)rr0 * 32 + (col >> 1)] = hh;
                    g_xl[(size_t)rr0 * 32 + (col >> 1)] = ll;
                }
            }
            if (rr1 < NN) {
                float o2 = (h1[nt] - mub) * scb * gx + bx;
                float o3 = (C[nt][3] - mub) * scb * gy + by;
                if (FINAL) {
                    ls[2 * nt] += o2; ls[2 * nt + 1] += o3;
                    lm[2 * nt] = fmaxf(lm[2 * nt], o2);
                    lm[2 * nt + 1] = fmaxf(lm[2 * nt + 1], o3);
                } else {
                    __nv_bfloat162 hh, ll;
                    split2(o2, o3, hh, ll);
                    g_xh[(size_t)rr1 * 32 + (col >> 1)] = hh;
                    g_xl[(size_t)rr1 * 32 + (col >> 1)] = ll;
                }
            }
        }
    }

    if (FINAL) {
        __syncthreads();
        #pragma unroll
        for (int nt = 0; nt < 8; nt++) {
            int col = nt * 8 + cc;
            atomicAdd(&fsum[col], ls[2 * nt]);
            atomicAdd(&fsum[col + 1], ls[2 * nt + 1]);
            atomicMax(&fmax[col], encf(lm[2 * nt]));
            atomicMax(&fmax[col + 1], encf(lm[2 * nt + 1]));
        }
        __syncthreads();
        if (tid < 64) {
            atomicAdd(&g_sum[tid], fsum[tid]);
            atomicMax(&g_maxb[tid], fmax[tid]);
        }
    }
}

__global__ void k_final(float* out) {
    int t = threadIdx.x;
    if (t < 64) out[t] = g_sum[t] * (1.0f / NN);
    else        out[t] = decf(g_maxb[t - 64]);
}

// ---------- launch ----------
extern "C" void kernel_launch(void* const* d_in, const int* in_sizes, int n_in,
                              void* d_out, int out_size) {
    const int*   ti    = (const int*)d_in[0];
    const int*   edges = (const int*)d_in[1];
    const float* et    = (const float*)d_in[2];
    const float* msg_w = (const float*)d_in[3];
    const float* msg_b = (const float*)d_in[4];
    const float* upd_w = (const float*)d_in[5];
    const float* upd_b = (const float*)d_in[6];
    const float* lng   = (const float*)d_in[7];
    const float* lnb   = (const float*)d_in[8];
    float* out = (float*)d_out;

    cudaFuncSetAttribute(k_proj_t, cudaFuncAttributeMaxDynamicSharedMemorySize, SMEM_PROJT);
    cudaFuncSetAttribute(k_upd_t<false>, cudaFuncAttributeMaxDynamicSharedMemorySize, SMEM_UPDT);
    cudaFuncSetAttribute(k_upd_t<true>,  cudaFuncAttributeMaxDynamicSharedMemorySize, SMEM_UPDT);

    k_setup<<<512, 256>>>(ti, et, msg_w, upd_w);
    k_hist<<<512, 256>>>(edges);
    k_scan1<<<NBLK, 256>>>();
    // layer-0 proj placed 4th so ncu (-s5 -c1) profiles it
    k_proj_t<<<296, 256, SMEM_PROJT>>>(0, msg_b);
    k_scan2<<<1, 512>>>();
    k_scan3<<<392, 256>>>();
    k_scatter<<<(NE + 255) / 256, 256>>>(edges);

    for (int l = 0; l < 3; l++) {
        if (l > 0) k_proj_t<<<296, 256, SMEM_PROJT>>>(l, msg_b + l * 64);
        k_edge<<<NN * 8 / NT, NT>>>();
        if (l < 2)
            k_upd_t<false><<<296, 256, SMEM_UPDT>>>(l, upd_b + l * 64, lng + l * 64, lnb + l * 64);
        else
            k_upd_t<true><<<296, 256, SMEM_UPDT>>>(l, upd_b + l * 64, lng + l * 64, lnb + l * 64);
    }

    k_final<<<1, 128>>>(out);
}

// round 17
// speedup vs baseline: 1.0287x; 1.0287x over previous
#include <cuda_runtime.h>
#include <cuda_bf16.h>
#include <cstdint>

#define NN 100000
#define NE 800000
#define H  64
#define NT 256
#define NBLK 391
#define PPIT 144   // proj smem row pitch bytes (72 bf16)
#define UPIT 272   // upd smem row pitch bytes (136 bf16)
#define UPD_GRID 296

#define SMEM_PROJT (4 * 128 * PPIT)                          // AH AL BH BL
#define SMEM_UPDT  (2 * 128 * UPIT + 2 * 64 * UPIT + 1296)   // AH AL BH BL + params + final acc + flag

// Scratch (device globals: allocation-free rule)
__device__ __align__(16) float g_p1[(size_t)NN * H];
__device__ __align__(16) float g_p2[(size_t)NN * H];
__device__ __align__(16) __nv_bfloat162 g_xh[(size_t)NN * 32];
__device__ __align__(16) __nv_bfloat162 g_xl[(size_t)NN * 32];
__device__ __align__(16) __nv_bfloat162 g_ah[(size_t)NN * 32];
__device__ __align__(16) __nv_bfloat162 g_al[(size_t)NN * 32];
__device__ __align__(16) __nv_bfloat16 g_bh[3 * 128 * 72];   // proj W hi [C][k] pitch 72
__device__ __align__(16) __nv_bfloat16 g_bl[3 * 128 * 72];
__device__ __align__(16) __nv_bfloat16 g_uh[3 * 64 * 136];   // upd W hi [C][k] pitch 136
__device__ __align__(16) __nv_bfloat16 g_ul[3 * 64 * 136];
__device__ int g_deg[NN];
__device__ int g_off[NN + 1];
__device__ int g_cur[NN];
__device__ int g_csr[NE];
__device__ int g_bsum[NBLK];
__device__ int g_boff[NBLK];
__device__ float g_sum[H];
__device__ unsigned g_maxb[H];
__device__ unsigned g_done;

// ---------- helpers ----------
__device__ __forceinline__ unsigned encf(float f) {
    unsigned u = __float_as_uint(f);
    return (u & 0x80000000u) ? ~u : (u | 0x80000000u);
}
__device__ __forceinline__ float decf(unsigned u) {
    return (u & 0x80000000u) ? __uint_as_float(u & 0x7FFFFFFFu) : __uint_as_float(~u);
}
__device__ __forceinline__ void split2(float a, float b, __nv_bfloat162& h, __nv_bfloat162& lo) {
    __nv_bfloat16 ha = __float2bfloat16(a), hb = __float2bfloat16(b);
    h = __halves2bfloat162(ha, hb);
    lo = __halves2bfloat162(__float2bfloat16(a - __bfloat162float(ha)),
                            __float2bfloat16(b - __bfloat162float(hb)));
}
__device__ __forceinline__ void ldsm4(unsigned* r, uint32_t addr) {
    asm volatile("ldmatrix.sync.aligned.m8n8.x4.shared.b16 {%0,%1,%2,%3}, [%4];"
                 : "=r"(r[0]), "=r"(r[1]), "=r"(r[2]), "=r"(r[3]) : "r"(addr));
}
__device__ __forceinline__ void mma16816(float* c, const unsigned* a, const unsigned* b) {
    asm volatile("mma.sync.aligned.m16n8k16.row.col.f32.bf16.bf16.f32 "
                 "{%0,%1,%2,%3}, {%4,%5,%6,%7}, {%8,%9}, {%0,%1,%2,%3};"
                 : "+f"(c[0]), "+f"(c[1]), "+f"(c[2]), "+f"(c[3])
                 : "r"(a[0]), "r"(a[1]), "r"(a[2]), "r"(a[3]), "r"(b[0]), "r"(b[1]));
}
__device__ __forceinline__ void cpa16(void* dst, const void* src) {
    unsigned d = (unsigned)__cvta_generic_to_shared(dst);
    asm volatile("cp.async.ca.shared.global [%0], [%1], 16;" :: "r"(d), "l"(src));
}
#define CPA_COMMIT() asm volatile("cp.async.commit_group;")
#define CPA_WAIT0()  asm volatile("cp.async.wait_group 0;")

// ---------- merged setup: embed + weight prepack ----------
__global__ void k_setup(const int* __restrict__ ti, const float* __restrict__ et,
                        const float* __restrict__ msg_w, const float* __restrict__ upd_w) {
    int i = blockIdx.x * blockDim.x + threadIdx.x;
    int stride = gridDim.x * blockDim.x;
    for (int n = i; n < NN; n += stride) g_deg[n] = 0;
    if (i < H) { g_sum[i] = 0.f; g_maxb[i] = 0u; }
    if (i == 0) g_done = 0u;
    for (int lin = i; lin < NN * 16; lin += stride) {
        int n = lin >> 4, q = lin & 15;
        float4 v = ((const float4*)et)[ti[n] * 16 + q];
        __nv_bfloat162 h0, l0, h1, l1;
        split2(v.x, v.y, h0, l0);
        split2(v.z, v.w, h1, l1);
        g_xh[lin * 2] = h0; g_xh[lin * 2 + 1] = h1;
        g_xl[lin * 2] = l0; g_xl[lin * 2 + 1] = l1;
    }
    for (int idx = i; idx < 3 * 128 * 72; idx += stride) {
        int l = idx / (128 * 72), r = idx % (128 * 72);
        int C = r / 72, k = r % 72;
        __nv_bfloat16 h = __float2bfloat16(0.f), lo = h;
        if (k < 64) {
            float v = msg_w[l * 8192 + (k + (C & 64)) * 64 + (C & 63)];
            h = __float2bfloat16(v);
            lo = __float2bfloat16(v - __bfloat162float(h));
        }
        g_bh[idx] = h; g_bl[idx] = lo;
    }
    for (int idx = i; idx < 3 * 64 * 136; idx += stride) {
        int l = idx / (64 * 136), r = idx % (64 * 136);
        int C = r / 136, k = r % 136;
        __nv_bfloat16 h = __float2bfloat16(0.f), lo = h;
        if (k < 128) {
            float v = upd_w[l * 8192 + k * 64 + C];
            h = __float2bfloat16(v);
            lo = __float2bfloat16(v - __bfloat162float(h));
        }
        g_uh[idx] = h; g_ul[idx] = lo;
    }
}

__global__ void k_hist(const int* __restrict__ edges) {
    int i = blockIdx.x * blockDim.x + threadIdx.x;
    int stride = gridDim.x * blockDim.x;
    for (int e = i; e < NE; e += stride)
        atomicAdd(&g_deg[((const int2*)edges)[e].y], 1);
}

// ---------- exclusive scan ----------
__global__ void k_scan1() {
    __shared__ int s[256];
    int t = threadIdx.x;
    int i = blockIdx.x * 256 + t;
    int v = (i < NN) ? g_deg[i] : 0;
    s[t] = v;
    __syncthreads();
    #pragma unroll
    for (int d = 1; d < 256; d <<= 1) {
        int tv = (t >= d) ? s[t - d] : 0;
        __syncthreads();
        s[t] += tv;
        __syncthreads();
    }
    if (i < NN) g_off[i] = s[t] - v;
    if (t == 255) g_bsum[blockIdx.x] = s[255];
}

__global__ void k_scan2() {
    __shared__ int s[512];
    int t = threadIdx.x;
    int v = (t < NBLK) ? g_bsum[t] : 0;
    s[t] = v;
    __syncthreads();
    #pragma unroll
    for (int d = 1; d < 512; d <<= 1) {
        int tv = (t >= d) ? s[t - d] : 0;
        __syncthreads();
        s[t] += tv;
        __syncthreads();
    }
    if (t < NBLK) g_boff[t] = s[t] - v;
}

__global__ void k_scan3() {
    int i = blockIdx.x * blockDim.x + threadIdx.x;
    if (i < NN) {
        int val = g_off[i] + g_boff[i >> 8];
        g_off[i] = val;
        g_cur[i] = val;
    }
    if (i == 0) g_off[NN] = NE;
}

__global__ void k_scatter(const int* __restrict__ edges) {
    int e = blockIdx.x * blockDim.x + threadIdx.x;
    if (e < NE) {
        int2 ed = ((const int2*)edges)[e];
        int pos = atomicAdd(&g_cur[ed.y], 1);
        g_csr[pos] = ed.x;
    }
}

// ---------- tensor-core projection (16-row warp tiling) ----------
__global__ __launch_bounds__(256, 2) void k_proj_t(int layer, const float* __restrict__ msg_b) {
    extern __shared__ char smc[];
    char* AH = smc;
    char* AL = AH + 128 * PPIT;
    char* BH = AL + 128 * PPIT;
    char* BL = BH + 128 * PPIT;

    const int tid = threadIdx.x;
    const int w = tid >> 5, l = tid & 31;

    {
        const uint4* sh = (const uint4*)(g_bh + layer * 128 * 72);
        const uint4* sl = (const uint4*)(g_bl + layer * 128 * 72);
        for (int i = tid; i < 1152; i += 256) {
            ((uint4*)BH)[i] = sh[i];
            ((uint4*)BL)[i] = sl[i];
        }
    }
    float2 bias2[8];
    #pragma unroll
    for (int i = 0; i < 8; i++) bias2[i] = *(const float2*)(msg_b + i * 8 + (l & 3) * 2);

    const uint32_t a_loff = (uint32_t)(((w << 4) + (l & 15)) * PPIT) + ((l >> 4) ? 16u : 0u);
    const uint32_t b_loff = (uint32_t)((l & 7) * PPIT) + (((l >> 3) & 1) ? 16u : 0u)
                          + (((l >> 4) & 1) ? 8u * PPIT : 0u);
    const uint32_t aH = (uint32_t)__cvta_generic_to_shared(AH) + a_loff;
    const uint32_t aL = (uint32_t)__cvta_generic_to_shared(AL) + a_loff;
    const uint32_t bH = (uint32_t)__cvta_generic_to_shared(BH) + b_loff;
    const uint32_t bL = (uint32_t)__cvta_generic_to_shared(BL) + b_loff;

    const uint4* xh4 = (const uint4*)g_xh;
    const uint4* xl4 = (const uint4*)g_xl;

    const int ntiles = (NN + 127) / 128;

    auto stageA = [&](int base) {
        #pragma unroll
        for (int s = 0; s < 4; s++) {
            int i = s * 256 + tid;
            int r = i >> 3, q = i & 7;
            int gn = base + r; if (gn >= NN) gn = NN - 1;
            cpa16(AH + r * PPIT + q * 16, &xh4[gn * 8 + q]);
            cpa16(AL + r * PPIT + q * 16, &xl4[gn * 8 + q]);
        }
    };

    if (blockIdx.x < ntiles) stageA(blockIdx.x * 128);
    CPA_COMMIT();

    for (int tile = blockIdx.x; tile < ntiles; tile += gridDim.x) {
        const int base = tile * 128;
        CPA_WAIT0();
        __syncthreads();

        float C[16][4];
        #pragma unroll
        for (int nt = 0; nt < 16; nt++) {
            C[nt][0] = 0.f; C[nt][1] = 0.f; C[nt][2] = 0.f; C[nt][3] = 0.f;
        }

        #pragma unroll
        for (int ks = 0; ks < 4; ks++) {
            unsigned Ah[4], Al4[4];
            ldsm4(Ah, aH + ks * 32);
            ldsm4(Al4, aL + ks * 32);
            #pragma unroll
            for (int ntp = 0; ntp < 8; ntp++) {
                unsigned Bh[4], Bl[4];
                ldsm4(Bh, bH + ntp * 16 * PPIT + ks * 32);
                ldsm4(Bl, bL + ntp * 16 * PPIT + ks * 32);
                mma16816(C[2 * ntp],     Ah,  Bh);
                mma16816(C[2 * ntp],     Ah,  Bl);
                mma16816(C[2 * ntp],     Al4, Bh);
                mma16816(C[2 * ntp + 1], Ah,  Bh + 2);
                mma16816(C[2 * ntp + 1], Ah,  Bl + 2);
                mma16816(C[2 * ntp + 1], Al4, Bh + 2);
            }
        }
        __syncthreads();

        int nxt = tile + gridDim.x;
        if (nxt < ntiles) stageA(nxt * 128);
        CPA_COMMIT();

        int r0 = base + (w << 4) + (l >> 2);
        int r1 = r0 + 8;
        int cc = (l & 3) * 2;
        #pragma unroll
        for (int nt = 0; nt < 8; nt++) {
            int col = nt * 8 + cc;
            if (r0 < NN) *(float2*)(g_p1 + (size_t)r0 * H + col) = make_float2(C[nt][0], C[nt][1]);
            if (r1 < NN) *(float2*)(g_p1 + (size_t)r1 * H + col) = make_float2(C[nt][2], C[nt][3]);
        }
        #pragma unroll
        for (int nt = 8; nt < 16; nt++) {
            int col = (nt - 8) * 8 + cc;
            float2 bb = bias2[nt - 8];
            if (r0 < NN) *(float2*)(g_p2 + (size_t)r0 * H + col) =
                make_float2(C[nt][0] + bb.x, C[nt][1] + bb.y);
            if (r1 < NN) *(float2*)(g_p2 + (size_t)r1 * H + col) =
                make_float2(C[nt][2] + bb.x, C[nt][3] + bb.y);
        }
    }
}

// ---------- CSR edge pass (2-way unrolled): agg[n] -> bf16 hi/lo ----------
__global__ __launch_bounds__(NT) void k_edge() {
    int idx = blockIdx.x * NT + threadIdx.x;
    int n = idx >> 3, q = idx & 7;
    int s0 = g_off[n], s1 = g_off[n + 1];
    const float4* p2 = (const float4*)(g_p2 + (size_t)n * H) + q * 2;
    float4 b0 = p2[0], b1 = p2[1];
    float a[8] = {0.f, 0.f, 0.f, 0.f, 0.f, 0.f, 0.f, 0.f};
    int i = s0;
    for (; i + 2 <= s1; i += 2) {
        int src0 = g_csr[i], src1 = g_csr[i + 1];
        const float4* pa = (const float4*)(g_p1 + (size_t)src0 * H) + q * 2;
        const float4* pb = (const float4*)(g_p1 + (size_t)src1 * H) + q * 2;
        float4 c0 = pa[0], c1 = pa[1];
        float4 d0 = pb[0], d1 = pb[1];
        a[0] += fmaxf(c0.x + b0.x, 0.f) + fmaxf(d0.x + b0.x, 0.f);
        a[1] += fmaxf(c0.y + b0.y, 0.f) + fmaxf(d0.y + b0.y, 0.f);
        a[2] += fmaxf(c0.z + b0.z, 0.f) + fmaxf(d0.z + b0.z, 0.f);
        a[3] += fmaxf(c0.w + b0.w, 0.f) + fmaxf(d0.w + b0.w, 0.f);
        a[4] += fmaxf(c1.x + b1.x, 0.f) + fmaxf(d1.x + b1.x, 0.f);
        a[5] += fmaxf(c1.y + b1.y, 0.f) + fmaxf(d1.y + b1.y, 0.f);
        a[6] += fmaxf(c1.z + b1.z, 0.f) + fmaxf(d1.z + b1.z, 0.f);
        a[7] += fmaxf(c1.w + b1.w, 0.f) + fmaxf(d1.w + b1.w, 0.f);
    }
    if (i < s1) {
        int src = g_csr[i];
        const float4* p1 = (const float4*)(g_p1 + (size_t)src * H) + q * 2;
        float4 c0 = p1[0], c1 = p1[1];
        a[0] += fmaxf(c0.x + b0.x, 0.f); a[1] += fmaxf(c0.y + b0.y, 0.f);
        a[2] += fmaxf(c0.z + b0.z, 0.f); a[3] += fmaxf(c0.w + b0.w, 0.f);
        a[4] += fmaxf(c1.x + b1.x, 0.f); a[5] += fmaxf(c1.y + b1.y, 0.f);
        a[6] += fmaxf(c1.z + b1.z, 0.f); a[7] += fmaxf(c1.w + b1.w, 0.f);
    }
    float ic = 1.0f / fmaxf((float)(s1 - s0), 1.0f);
    __nv_bfloat162 h[4], lo[4];
    #pragma unroll
    for (int j = 0; j < 4; j++) split2(a[2 * j] * ic, a[2 * j + 1] * ic, h[j], lo[j]);
    *(uint4*)(g_ah + (size_t)n * 32 + q * 4) = *(uint4*)h;
    *(uint4*)(g_al + (size_t)n * 32 + q * 4) = *(uint4*)lo;
}

// ---------- tensor-core update + residual (smem) + LayerNorm (+fused final output) ----------
template <bool FINAL>
__global__ __launch_bounds__(256, 2) void k_upd_t(int layer, const float* __restrict__ B,
                                                  const float* __restrict__ lng,
                                                  const float* __restrict__ lnb,
                                                  float* __restrict__ out) {
    extern __shared__ char smc[];
    char* AH = smc;
    char* AL = AH + 128 * UPIT;
    char* BH = AL + 128 * UPIT;
    char* BL = BH + 64 * UPIT;
    float* prm = (float*)(BL + 64 * UPIT);           // bias[64], g[64], b2[64] = 768 B
    float* fsum = prm + 192;                          // 256 B
    unsigned* fmax = (unsigned*)(fsum + 64);          // 256 B
    unsigned* flast = fmax + 64;                      // 4 B (within the 1296-B tail)

    const int tid = threadIdx.x;
    const int w = tid >> 5, l = tid & 31;

    {
        const uint4* sh = (const uint4*)(g_uh + layer * 64 * 136);
        const uint4* sl = (const uint4*)(g_ul + layer * 64 * 136);
        for (int i = tid; i < 1088; i += 256) {
            ((uint4*)BH)[i] = sh[i];
            ((uint4*)BL)[i] = sl[i];
        }
        if (tid < 64) {
            prm[tid] = B[tid];
            prm[64 + tid] = lng[tid];
            prm[128 + tid] = lnb[tid];
            if (FINAL) { fsum[tid] = 0.f; fmax[tid] = 0u; }
        }
    }

    const uint32_t a_loff = (uint32_t)(((w << 4) + (l & 15)) * UPIT) + ((l >> 4) ? 16u : 0u);
    const uint32_t b_loff = (uint32_t)((l & 7) * UPIT) + (((l >> 3) & 1) ? 16u : 0u)
                          + (((l >> 4) & 1) ? 8u * UPIT : 0u);
    const uint32_t aH = (uint32_t)__cvta_generic_to_shared(AH) + a_loff;
    const uint32_t aL = (uint32_t)__cvta_generic_to_shared(AL) + a_loff;
    const uint32_t bH = (uint32_t)__cvta_generic_to_shared(BH) + b_loff;
    const uint32_t bL = (uint32_t)__cvta_generic_to_shared(BL) + b_loff;

    const uint4* xh4 = (const uint4*)g_xh;
    const uint4* xl4 = (const uint4*)g_xl;
    const uint4* ah4 = (const uint4*)g_ah;
    const uint4* al4 = (const uint4*)g_al;

    const int ntiles = (NN + 127) / 128;

    auto stageA = [&](int base) {
        #pragma unroll
        for (int s = 0; s < 8; s++) {
            int i = s * 256 + tid;
            int r = i >> 4, q = i & 15;
            int gn = base + r; if (gn >= NN) gn = NN - 1;
            const uint4* srch = (q < 8) ? &xh4[gn * 8 + q] : &ah4[gn * 8 + (q - 8)];
            const uint4* srcl = (q < 8) ? &xl4[gn * 8 + q] : &al4[gn * 8 + (q - 8)];
            cpa16(AH + r * UPIT + q * 16, srch);
            cpa16(AL + r * UPIT + q * 16, srcl);
        }
    };

    float ls[16], lm[16];
    if (FINAL) {
        #pragma unroll
        for (int i = 0; i < 16; i++) { ls[i] = 0.f; lm[i] = -3.402823466e38f; }
    }

    if (blockIdx.x < ntiles) stageA(blockIdx.x * 128);
    CPA_COMMIT();

    const int lr0 = (w << 4) + (l >> 2);
    const int lr1 = lr0 + 8;
    const int cc = (l & 3) * 2;

    for (int tile = blockIdx.x; tile < ntiles; tile += gridDim.x) {
        const int base = tile * 128;
        CPA_WAIT0();
        __syncthreads();

        float C[8][4];
        #pragma unroll
        for (int nt = 0; nt < 8; nt++) {
            C[nt][0] = 0.f; C[nt][1] = 0.f; C[nt][2] = 0.f; C[nt][3] = 0.f;
        }

        #pragma unroll
        for (int ks = 0; ks < 8; ks++) {
            unsigned Ah[4], Al4r[4];
            ldsm4(Ah, aH + ks * 32);
            ldsm4(Al4r, aL + ks * 32);
            #pragma unroll
            for (int ntp = 0; ntp < 4; ntp++) {
                unsigned Bh[4], Bl[4];
                ldsm4(Bh, bH + ntp * 16 * UPIT + ks * 32);
                ldsm4(Bl, bL + ntp * 16 * UPIT + ks * 32);
                mma16816(C[2 * ntp],     Ah,   Bh);
                mma16816(C[2 * ntp],     Ah,   Bl);
                mma16816(C[2 * ntp],     Al4r, Bh);
                mma16816(C[2 * ntp + 1], Ah,   Bh + 2);
                mma16816(C[2 * ntp + 1], Ah,   Bl + 2);
                mma16816(C[2 * ntp + 1], Al4r, Bh + 2);
            }
        }
        __syncthreads();

        // residual x = xh + xl from smem (x-half of this tile's A)
        float rx0[16], rx1[16];
        #pragma unroll
        for (int nt = 0; nt < 8; nt++) {
            int boff = (nt * 8 + cc) * 2;
            __nv_bfloat162 h0 = *(__nv_bfloat162*)(AH + lr0 * UPIT + boff);
            __nv_bfloat162 l0 = *(__nv_bfloat162*)(AL + lr0 * UPIT + boff);
            __nv_bfloat162 h1 = *(__nv_bfloat162*)(AH + lr1 * UPIT + boff);
            __nv_bfloat162 l1 = *(__nv_bfloat162*)(AL + lr1 * UPIT + boff);
            rx0[2 * nt]     = __bfloat162float(h0.x) + __bfloat162float(l0.x);
            rx0[2 * nt + 1] = __bfloat162float(h0.y) + __bfloat162float(l0.y);
            rx1[2 * nt]     = __bfloat162float(h1.x) + __bfloat162float(l1.x);
            rx1[2 * nt + 1] = __bfloat162float(h1.y) + __bfloat162float(l1.y);
        }
        __syncthreads();

        int nxt = tile + gridDim.x;
        if (nxt < ntiles) stageA(nxt * 128);
        CPA_COMMIT();

        int rr0 = base + lr0;
        int rr1 = base + lr1;
        float h0[8], h1[8];
        float s1a = 0.f, s2a = 0.f, s1b = 0.f, s2b = 0.f;
        #pragma unroll
        for (int nt = 0; nt < 8; nt++) {
            int col = nt * 8 + cc;
            float bx = prm[col], by = prm[col + 1];
            float v0 = fmaxf(C[nt][0] + bx, 0.f) + rx0[2 * nt];
            float v1 = fmaxf(C[nt][1] + by, 0.f) + rx0[2 * nt + 1];
            float v2 = fmaxf(C[nt][2] + bx, 0.f) + rx1[2 * nt];
            float v3 = fmaxf(C[nt][3] + by, 0.f) + rx1[2 * nt + 1];
            h0[nt] = v0; h1[nt] = v2;
            s1a += v0 + v1; s2a += v0 * v0 + v1 * v1;
            s1b += v2 + v3; s2b += v2 * v2 + v3 * v3;
            C[nt][1] = v1; C[nt][3] = v3;
        }
        #pragma unroll
        for (int d = 1; d < 4; d <<= 1) {
            s1a += __shfl_xor_sync(0xFFFFFFFFu, s1a, d);
            s2a += __shfl_xor_sync(0xFFFFFFFFu, s2a, d);
            s1b += __shfl_xor_sync(0xFFFFFFFFu, s1b, d);
            s2b += __shfl_xor_sync(0xFFFFFFFFu, s2b, d);
        }
        float mua = s1a * 0.015625f, mub = s1b * 0.015625f;
        float sca = rsqrtf(fmaxf(s2a * 0.015625f - mua * mua, 0.f) + 1e-5f);
        float scb = rsqrtf(fmaxf(s2b * 0.015625f - mub * mub, 0.f) + 1e-5f);
        #pragma unroll
        for (int nt = 0; nt < 8; nt++) {
            int col = nt * 8 + cc;
            float gx = prm[64 + col], gy = prm[65 + col];
            float bx = prm[128 + col], by = prm[129 + col];
            if (rr0 < NN) {
                float o0 = (h0[nt] - mua) * sca * gx + bx;
                float o1 = (C[nt][1] - mua) * sca * gy + by;
                if (FINAL) {
                    ls[2 * nt] += o0; ls[2 * nt + 1] += o1;
                    lm[2 * nt] = fmaxf(lm[2 * nt], o0);
                    lm[2 * nt + 1] = fmaxf(lm[2 * nt + 1], o1);
                } else {
                    __nv_bfloat162 hh, ll;
                    split2(o0, o1, hh, ll);
                    g_xh[(size_t)rr0 * 32 + (col >> 1)] = hh;
                    g_xl[(size_t)rr0 * 32 + (col >> 1)] = ll;
                }
            }
            if (rr1 < NN) {
                float o2 = (h1[nt] - mub) * scb * gx + bx;
                float o3 = (C[nt][3] - mub) * scb * gy + by;
                if (FINAL) {
                    ls[2 * nt] += o2; ls[2 * nt + 1] += o3;
                    lm[2 * nt] = fmaxf(lm[2 * nt], o2);
                    lm[2 * nt + 1] = fmaxf(lm[2 * nt + 1], o3);
                } else {
                    __nv_bfloat162 hh, ll;
                    split2(o2, o3, hh, ll);
                    g_xh[(size_t)rr1 * 32 + (col >> 1)] = hh;
                    g_xl[(size_t)rr1 * 32 + (col >> 1)] = ll;
                }
            }
        }
    }

    if (FINAL) {
        __syncthreads();
        #pragma unroll
        for (int nt = 0; nt < 8; nt++) {
            int col = nt * 8 + cc;
            atomicAdd(&fsum[col], ls[2 * nt]);
            atomicAdd(&fsum[col + 1], ls[2 * nt + 1]);
            atomicMax(&fmax[col], encf(lm[2 * nt]));
            atomicMax(&fmax[col + 1], encf(lm[2 * nt + 1]));
        }
        __syncthreads();
        if (tid < 64) {
            atomicAdd(&g_sum[tid], fsum[tid]);
            atomicMax(&g_maxb[tid], fmax[tid]);
        }
        __syncthreads();
        if (tid == 0) {
            __threadfence();
            unsigned prev = atomicAdd(&g_done, 1u);
            flast[0] = (prev == gridDim.x - 1) ? 1u : 0u;
        }
        __syncthreads();
        if (flast[0]) {
            __threadfence();
            if (tid < 64) {
                volatile float* vs = g_sum;
                out[tid] = vs[tid] * (1.0f / NN);
            } else if (tid < 128) {
                volatile unsigned* vm = g_maxb;
                out[tid] = decf(vm[tid - 64]);
            }
        }
    }
}

// ---------- launch ----------
extern "C" void kernel_launch(void* const* d_in, const int* in_sizes, int n_in,
                              void* d_out, int out_size) {
    const int*   ti    = (const int*)d_in[0];
    const int*   edges = (const int*)d_in[1];
    const float* et    = (const float*)d_in[2];
    const float* msg_w = (const float*)d_in[3];
    const float* msg_b = (const float*)d_in[4];
    const float* upd_w = (const float*)d_in[5];
    const float* upd_b = (const float*)d_in[6];
    const float* lng   = (const float*)d_in[7];
    const float* lnb   = (const float*)d_in[8];
    float* out = (float*)d_out;

    cudaFuncSetAttribute(k_proj_t, cudaFuncAttributeMaxDynamicSharedMemorySize, SMEM_PROJT);
    cudaFuncSetAttribute(k_upd_t<false>, cudaFuncAttributeMaxDynamicSharedMemorySize, SMEM_UPDT);
    cudaFuncSetAttribute(k_upd_t<true>,  cudaFuncAttributeMaxDynamicSharedMemorySize, SMEM_UPDT);

    k_setup<<<512, 256>>>(ti, et, msg_w, upd_w);
    k_hist<<<512, 256>>>(edges);
    k_scan1<<<NBLK, 256>>>();
    // layer-0 proj placed 4th so ncu (-s5 -c1) profiles it
    k_proj_t<<<296, 256, SMEM_PROJT>>>(0, msg_b);
    k_scan2<<<1, 512>>>();
    k_scan3<<<392, 256>>>();
    k_scatter<<<(NE + 255) / 256, 256>>>(edges);

    for (int l = 0; l < 3; l++) {
        if (l > 0) k_proj_t<<<296, 256, SMEM_PROJT>>>(l, msg_b + l * 64);
        k_edge<<<NN * 8 / NT, NT>>>();
        if (l < 2)
            k_upd_t<false><<<UPD_GRID, 256, SMEM_UPDT>>>(l, upd_b + l * 64,
                                                         lng + l * 64, lnb + l * 64, out);
        else
            k_upd_t<true><<<UPD_GRID, 256, SMEM_UPDT>>>(l, upd_b + l * 64,
                                                        lng + l * 64, lnb + l * 64, out);
    }
}